// round 13
// baseline (speedup 1.0000x reference)
#include <cuda_runtime.h>
#include <stdint.h>

#define HW   16384
#define CIN  64
#define COUT 64
#define NGRP 16
#define XP   20      // IMMA transpose pitch (words)
#define WP   20      // IMMA weight pitch (words)
#define CPP  132     // IMMA raw-C pitch [ch][pos]

__device__ __forceinline__ unsigned pack4(int a, int b, int c, int d) {
    unsigned lo = __byte_perm((unsigned)a, (unsigned)b, 0x0040);
    unsigned hi = __byte_perm((unsigned)c, (unsigned)d, 0x0040);
    return __byte_perm(lo, hi, 0x5410);
}

__device__ __forceinline__ int dp4a_us(unsigned a, int b, int c) {
    int r;
    asm("dp4a.u32.s32 %0, %1, %2, %3;" : "=r"(r) : "r"(a), "r"(b), "r"(c));
    return r;
}

__device__ __forceinline__ void mma_u8s8(int& c0, int& c1, int& c2, int& c3,
                                         unsigned a0, unsigned a1, unsigned a2,
                                         unsigned a3, unsigned b0, unsigned b1) {
    asm("mma.sync.aligned.m16n8k32.row.col.s32.u8.s8.s32 "
        "{%0,%1,%2,%3}, {%4,%5,%6,%7}, {%8,%9}, {%0,%1,%2,%3};"
        : "+r"(c0), "+r"(c1), "+r"(c2), "+r"(c3)
        : "r"(a0), "r"(a1), "r"(a2), "r"(a3), "r"(b0), "r"(b1));
}

__global__ __launch_bounds__(256, 3) void conv_hybrid(
    const int*   __restrict__ x,
    float*       __restrict__ out,
    const int4*  __restrict__ w,
    const float* __restrict__ wscale,
    const int*   __restrict__ wzp,
    const float* __restrict__ bias,
    const float* __restrict__ iscale,
    const float* __restrict__ oscale,
    const int*   __restrict__ izp_p,
    const int*   __restrict__ ozp_p)
{
    __shared__ uint32_t s_big[COUT * CPP];
    __shared__ uint32_t s_w2[COUT * WP];
    __shared__ float4   s_P[COUT];
    __shared__ float    s_sx[128];

    const int tid = threadIdx.x;
    const int bid = blockIdx.x;

    if (bid % 3 == 0) {
        // ===== dp4a path: 1 position/thread, 256 positions/block ==========
        // images 0..15 : 1024 blocks x 256 positions = 262144 positions
        const int chunk = bid / 3;            // 0..1023
        int* s_wd = (int*)s_big;

        if (tid < COUT) {
            const int o = tid;
            int sum = 0;
#pragma unroll
            for (int g = 0; g < NGRP; g++) {
                int4 v = __ldg(w + o * NGRP + g);
                sum += v.x + v.y + v.z + v.w;
                s_wd[g * COUT + o] = (int)pack4(v.x, v.y, v.z, v.w);
            }
            float s   = iscale[0] * wscale[o] / oscale[0];
            float izp = (float)izp_p[0];
            float zw  = (float)wzp[o];
            float C0  = bias[o] / oscale[0]
                      + s * izp * (64.0f * zw - (float)sum)
                      + (float)ozp_p[0];
            s_P[o] = make_float4(s, C0, -s * zw, 0.0f);
        }
        __syncthreads();

        const int gp = chunk * 256 + tid;     // global position (images 0..15)
        const int b  = gp >> 14;
        const int hw = gp & (HW - 1);
        const int* xb = x + b * (CIN * HW) + hw;

        unsigned xw[NGRP];
#pragma unroll
        for (int g = 0; g < NGRP; g++) {
            int v0 = __ldg(xb + (g * 4 + 0) * HW);
            int v1 = __ldg(xb + (g * 4 + 1) * HW);
            int v2 = __ldg(xb + (g * 4 + 2) * HW);
            int v3 = __ldg(xb + (g * 4 + 3) * HW);
            xw[g] = pack4(v0, v1, v2, v3);
        }

        int sx = 0;
#pragma unroll
        for (int g = 0; g < NGRP; g++)
            sx = dp4a_us(xw[g], 0x01010101, sx);
        const float sxf = (float)sx;

        float* const ob = out + b * (COUT * HW) + hw;
#pragma unroll
        for (int q = 0; q < NGRP; q++) {
            int acc0 = 0, acc1 = 0, acc2 = 0, acc3 = 0;
#pragma unroll
            for (int g = 0; g < NGRP; g++) {
                int4 w4 = *(const int4*)(s_wd + g * COUT + q * 4);
                acc0 = dp4a_us(xw[g], w4.x, acc0);
                acc1 = dp4a_us(xw[g], w4.y, acc1);
                acc2 = dp4a_us(xw[g], w4.z, acc2);
                acc3 = dp4a_us(xw[g], w4.w, acc3);
            }
            int accs[4] = {acc0, acc1, acc2, acc3};
#pragma unroll
            for (int j = 0; j < 4; j++) {
                const int o = q * 4 + j;
                float4 P = s_P[o];
                float f = fmaf(P.x, (float)accs[j], fmaf(P.z, sxf, P.y));
                f = fminf(fmaxf(rintf(f), 0.0f), 255.0f);
                ob[o * HW] = f;
            }
        }
        return;
    }

    // ===== IMMA path (verbatim R11): images 16..31, 2048 blocks ===========
    const int T = 2048 + (bid - bid / 3 - 1);   // tiles 2048..4095

    if (tid < COUT) {
        const int o = tid;
        int sum = 0;
#pragma unroll
        for (int i = 0; i < 4; i++) {
            uint32_t wd[4];
#pragma unroll
            for (int j = 0; j < 4; j++) {
                int4 v = __ldg(w + o * 16 + i * 4 + j);
                sum += v.x + v.y + v.z + v.w;
                wd[j] = pack4(v.x, v.y, v.z, v.w);
            }
            *(uint4*)(s_w2 + o * WP + i * 4) = make_uint4(wd[0], wd[1], wd[2], wd[3]);
        }
        float S   = iscale[0] * wscale[o] / oscale[0];
        float izp = (float)__ldg(izp_p);
        float zw  = (float)__ldg(wzp + o);
        float C0  = bias[o] / oscale[0]
                  + S * izp * (64.0f * zw - (float)sum)
                  + (float)__ldg(ozp_p);
        s_P[o] = make_float4(S, C0, -S * zw, 0.0f);
    }

    const int bb  = T >> 7;
    const int hw0 = (T & 127) << 7;
    const int* xb = x + bb * (CIN * HW) + hw0;
#pragma unroll
    for (int it = 0; it < 2; it++) {
        int task = tid + 256 * it;
        int pos  = task & 127;
        int grp  = task >> 7;
        uint32_t wd[4];
#pragma unroll
        for (int j = 0; j < 4; j++) {
            const int* cp = xb + (grp * 16 + j * 4) * HW + pos;
            int v0 = __ldg(cp + 0 * HW);
            int v1 = __ldg(cp + 1 * HW);
            int v2 = __ldg(cp + 2 * HW);
            int v3 = __ldg(cp + 3 * HW);
            wd[j] = pack4(v0, v1, v2, v3);
        }
        *(uint4*)(s_big + pos * XP + grp * 4) = make_uint4(wd[0], wd[1], wd[2], wd[3]);
    }
    __syncthreads();

    const int wid  = tid >> 5;
    const int lane = tid & 31;
    const int g    = lane >> 2;
    const int t4   = lane & 3;
    const int r0   = wid * 16 + g;
    const int r1   = r0 + 8;

    unsigned a[2][4];
#pragma unroll
    for (int kt = 0; kt < 2; kt++) {
        int wb = t4 + 8 * kt;
        a[kt][0] = s_big[r0 * XP + wb];
        a[kt][1] = s_big[r1 * XP + wb];
        a[kt][2] = s_big[r0 * XP + wb + 4];
        a[kt][3] = s_big[r1 * XP + wb + 4];
    }

    int p0 = 0, p1 = 0;
    p0 = dp4a_us(a[0][0], 0x01010101, p0);
    p0 = dp4a_us(a[0][2], 0x01010101, p0);
    p0 = dp4a_us(a[1][0], 0x01010101, p0);
    p0 = dp4a_us(a[1][2], 0x01010101, p0);
    p1 = dp4a_us(a[0][1], 0x01010101, p1);
    p1 = dp4a_us(a[0][3], 0x01010101, p1);
    p1 = dp4a_us(a[1][1], 0x01010101, p1);
    p1 = dp4a_us(a[1][3], 0x01010101, p1);
    p0 += __shfl_xor_sync(0xffffffffu, p0, 1);
    p0 += __shfl_xor_sync(0xffffffffu, p0, 2);
    p1 += __shfl_xor_sync(0xffffffffu, p1, 1);
    p1 += __shfl_xor_sync(0xffffffffu, p1, 2);
    if (t4 == 0) {
        s_sx[r0] = (float)p0;
        s_sx[r1] = (float)p1;
    }
    __syncthreads();

#pragma unroll
    for (int nt = 0; nt < 8; nt++) {
        const uint32_t* wr = s_w2 + (nt * 8 + g) * WP + t4;
        unsigned b00 = wr[0];
        unsigned b01 = wr[4];
        unsigned b10 = wr[8];
        unsigned b11 = wr[12];
        int c0 = 0, c1 = 0, c2 = 0, c3 = 0;
        mma_u8s8(c0, c1, c2, c3, a[0][0], a[0][1], a[0][2], a[0][3], b00, b01);
        mma_u8s8(c0, c1, c2, c3, a[1][0], a[1][1], a[1][2], a[1][3], b10, b11);

        const int ch = nt * 8 + 2 * t4;
        s_big[(ch + 0) * CPP + r0] = (uint32_t)c0;
        s_big[(ch + 1) * CPP + r0] = (uint32_t)c1;
        s_big[(ch + 0) * CPP + r1] = (uint32_t)c2;
        s_big[(ch + 1) * CPP + r1] = (uint32_t)c3;
    }
    __syncthreads();

    const int pos = tid & 127;
    const int cb  = (tid >> 7) * 32;
    const float sxf = s_sx[pos];
    float* const ob = out + bb * (COUT * HW) + hw0 + pos;
#pragma unroll
    for (int j = 0; j < 32; j++) {
        const int ch = cb + j;
        int c = (int)s_big[ch * CPP + pos];
        float4 P = s_P[ch];
        float f = fmaf(P.x, (float)c, fmaf(P.z, sxf, P.y));
        f = fminf(fmaxf(rintf(f), 0.0f), 255.0f);
        ob[ch * HW] = f;
    }
}

extern "C" void kernel_launch(void* const* d_in, const int* in_sizes, int n_in,
                              void* d_out, int out_size) {
    // 0: x_quant (i32)  1: input_scale (f32)  2: input_zero_point (i32)
    // 3: weight_int8 (i32)  4: weight_scale (f32)  5: weight_zero_point (i32)
    // 6: bias_fp32 (f32)  7: output_scale (f32)  8: output_zero_point (i32)
    (void)in_sizes; (void)n_in; (void)out_size;

    // 3072 blocks: bid%3==0 -> dp4a (1024 blocks, images 0..15),
    //              else     -> IMMA (2048 blocks, images 16..31).
    // Equal per-block cost so the resident mix stays balanced to the tail.
    conv_hybrid<<<3072, 256>>>((const int*)d_in[0], (float*)d_out,
                               (const int4*)d_in[3], (const float*)d_in[4],
                               (const int*)d_in[5], (const float*)d_in[6],
                               (const float*)d_in[1], (const float*)d_in[7],
                               (const int*)d_in[2], (const int*)d_in[8]);
}

// round 14
// speedup vs baseline: 1.1126x; 1.1126x over previous
#include <cuda_runtime.h>
#include <stdint.h>

#define CIN    64
#define COUT   64
#define HW     16384
#define NGRP   16
#define MAGICF 12582912.0f     // 1.5 * 2^23
#define MAGICI 0x4B400000

__device__ __forceinline__ int dp4a_us(unsigned a, int b, int c) {
    int r;
    asm("dp4a.u32.s32 %0, %1, %2, %3;" : "=r"(r) : "r"(a), "r"(b), "r"(c));
    return r;
}

__device__ __forceinline__ unsigned pack4(int a, int b, int c, int d) {
    unsigned lo = __byte_perm((unsigned)a, (unsigned)b, 0x0040);
    unsigned hi = __byte_perm((unsigned)c, (unsigned)d, 0x0040);
    return __byte_perm(lo, hi, 0x5410);
}

template<bool HASZP>
__device__ __forceinline__ void conv_body(const int2* __restrict__ xb,
                                          float2* __restrict__ o2,
                                          int out_base,
                                          const int* s_w,
                                          const float4* s_P)
{
    // load 64 channels x 2 positions; pack to u8x4 words per (group, pos)
    unsigned xw[NGRP][2];
#pragma unroll
    for (int g = 0; g < NGRP; g++) {
        int2 a0 = __ldg(xb + (g * 4 + 0) * (HW / 2));
        int2 a1 = __ldg(xb + (g * 4 + 1) * (HW / 2));
        int2 a2 = __ldg(xb + (g * 4 + 2) * (HW / 2));
        int2 a3 = __ldg(xb + (g * 4 + 3) * (HW / 2));
        xw[g][0] = pack4(a0.x, a1.x, a2.x, a3.x);
        xw[g][1] = pack4(a0.y, a1.y, a2.y, a3.y);
    }

    float sxf0 = 0.0f, sxf1 = 0.0f;
    if (HASZP) {   // per-position channel sums needed only when wzp != 0
        int sx0 = 0, sx1 = 0;
#pragma unroll
        for (int g = 0; g < NGRP; g++) {
            sx0 = dp4a_us(xw[g][0], 0x01010101, sx0);
            sx1 = dp4a_us(xw[g][1], 0x01010101, sx1);
        }
        sxf0 = (float)sx0;
        sxf1 = (float)sx1;
    }

    for (int q = 0; q < NGRP; q++) {      // 16 output-channel quads
        int acc[4][2] = {};
        int4 w4 = *(const int4*)(s_w + q * 4);     // g = 0 prefetch
#pragma unroll
        for (int g = 0; g < NGRP; g++) {
            int4 cur = w4;
            if (g + 1 < NGRP)                      // one-ahead prefetch
                w4 = *(const int4*)(s_w + (g + 1) * COUT + q * 4);
            acc[0][0] = dp4a_us(xw[g][0], cur.x, acc[0][0]);
            acc[0][1] = dp4a_us(xw[g][1], cur.x, acc[0][1]);
            acc[1][0] = dp4a_us(xw[g][0], cur.y, acc[1][0]);
            acc[1][1] = dp4a_us(xw[g][1], cur.y, acc[1][1]);
            acc[2][0] = dp4a_us(xw[g][0], cur.z, acc[2][0]);
            acc[2][1] = dp4a_us(xw[g][1], cur.z, acc[2][1]);
            acc[3][0] = dp4a_us(xw[g][0], cur.w, acc[3][0]);
            acc[3][1] = dp4a_us(xw[g][1], cur.w, acc[3][1]);
        }
#pragma unroll
        for (int j = 0; j < 4; j++) {
            int o = q * 4 + j;
            float4 P = s_P[o];            // broadcast LDS.128: S, C0, C1
            float base0 = HASZP ? fmaf(P.z, sxf0, P.y) : P.y;
            float base1 = HASZP ? fmaf(P.z, sxf1, P.y) : P.y;
            float f0 = fmaf(P.x, (float)acc[j][0], base0);
            float f1 = fmaf(P.x, (float)acc[j][1], base1);
            // round-half-even via magic add; clamp in int domain (alu pipe)
            int r0 = __float_as_int(f0 + MAGICF);
            int r1 = __float_as_int(f1 + MAGICF);
            r0 = min(max(r0, MAGICI), MAGICI + 255);
            r1 = min(max(r1, MAGICI), MAGICI + 255);
            o2[out_base + o * (HW / 2)] =
                make_float2(__int_as_float(r0) - MAGICF,
                            __int_as_float(r1) - MAGICF);
        }
    }
}

__global__ __launch_bounds__(256, 3) void conv_fused(
    const int2*  __restrict__ x,
    float2*      __restrict__ out,
    const int4*  __restrict__ w,
    const float* __restrict__ wscale,
    const int*   __restrict__ wzp,
    const float* __restrict__ bias,
    const float* __restrict__ iscale,
    const float* __restrict__ oscale,
    const int*   __restrict__ izp_p,
    const int*   __restrict__ ozp_p)
{
    __shared__ int    s_w[NGRP * COUT];   // [group][o] packed s8 weights
    __shared__ float4 s_P[COUT];          // (S, C0, C1, 0) per output channel

    const int tid = threadIdx.x;
    int myzp = 0;

    // ---- inlined prep: threads 0..63 each build one output channel ----
    if (tid < COUT) {
        const int o = tid;
        int sum = 0;
#pragma unroll
        for (int g = 0; g < NGRP; g++) {
            int4 v = __ldg(w + o * NGRP + g);
            sum += v.x + v.y + v.z + v.w;
            s_w[g * COUT + o] = (int)pack4(v.x, v.y, v.z, v.w);
        }
        myzp = __ldg(wzp + o);
        float s   = iscale[0] * wscale[o] / oscale[0];
        float izp = (float)izp_p[0];
        float zw  = (float)myzp;
        // round(f)+ozp == round(f+ozp) for integer ozp -> fold ozp into C0
        float C0  = bias[o] / oscale[0]
                  + s * izp * (64.0f * zw - (float)sum)
                  + (float)ozp_p[0];
        s_P[o] = make_float4(s, C0, -s * zw, 0.0f);
    }
    // full barrier + block-wide OR of "any weight zero-point nonzero"
    const int haszp = __syncthreads_or(myzp != 0);

    int gp = (blockIdx.x * 256 + tid) << 1;  // 2 consecutive w positions
    int b  = gp >> 14;                        // / HW
    int hw = gp & (HW - 1);

    const int2* xb = x + (b * (CIN * HW / 2) + (hw >> 1));
    const int out_base = b * COUT * (HW / 2) + (hw >> 1);   // float2 units

    if (haszp)
        conv_body<true>(xb, out, out_base, s_w, s_P);
    else
        conv_body<false>(xb, out, out_base, s_w, s_P);
}

extern "C" void kernel_launch(void* const* d_in, const int* in_sizes, int n_in,
                              void* d_out, int out_size) {
    // 0: x_quant (i32)  1: input_scale (f32)  2: input_zero_point (i32)
    // 3: weight_int8 (i32)  4: weight_scale (f32)  5: weight_zero_point (i32)
    // 6: bias_fp32 (f32)  7: output_scale (f32)  8: output_zero_point (i32)
    (void)in_sizes; (void)n_in; (void)out_size;

    // 524288 positions / 2 per thread / 256 threads = 1024 blocks (exact)
    conv_fused<<<1024, 256>>>((const int2*)d_in[0], (float2*)d_out,
                              (const int4*)d_in[3], (const float*)d_in[4],
                              (const int*)d_in[5], (const float*)d_in[6],
                              (const float*)d_in[1], (const float*)d_in[7],
                              (const int*)d_in[2], (const int*)d_in[8]);
}

// round 15
// speedup vs baseline: 1.1305x; 1.0160x over previous
#include <cuda_runtime.h>
#include <stdint.h>

#define CIN    64
#define COUT   64
#define HW     16384
#define NGRP   16

__device__ __forceinline__ int dp4a_us(unsigned a, int b, int c) {
    int r;
    asm("dp4a.u32.s32 %0, %1, %2, %3;" : "=r"(r) : "r"(a), "r"(b), "r"(c));
    return r;
}

__device__ __forceinline__ unsigned pack4(int a, int b, int c, int d) {
    unsigned lo = __byte_perm((unsigned)a, (unsigned)b, 0x0040);
    unsigned hi = __byte_perm((unsigned)c, (unsigned)d, 0x0040);
    return __byte_perm(lo, hi, 0x5410);
}

template<bool HASZP>
__device__ __forceinline__ void conv_body(const int2* __restrict__ xb,
                                          float2* __restrict__ o2,
                                          int out_base,
                                          const int* s_w,
                                          const float4* s_P)
{
    // load 64 channels x 2 positions; pack to u8x4 words per (group, pos)
    unsigned xw[NGRP][2];
#pragma unroll
    for (int g = 0; g < NGRP; g++) {
        int2 a0 = __ldg(xb + (g * 4 + 0) * (HW / 2));
        int2 a1 = __ldg(xb + (g * 4 + 1) * (HW / 2));
        int2 a2 = __ldg(xb + (g * 4 + 2) * (HW / 2));
        int2 a3 = __ldg(xb + (g * 4 + 3) * (HW / 2));
        xw[g][0] = pack4(a0.x, a1.x, a2.x, a3.x);
        xw[g][1] = pack4(a0.y, a1.y, a2.y, a3.y);
    }

    // per-position channel sums only needed when any wzp != 0
    float sxf0 = 0.0f, sxf1 = 0.0f;
    if (HASZP) {
        int sx0 = 0, sx1 = 0;
#pragma unroll
        for (int g = 0; g < NGRP; g++) {
            sx0 = dp4a_us(xw[g][0], 0x01010101, sx0);
            sx1 = dp4a_us(xw[g][1], 0x01010101, sx1);
        }
        sxf0 = (float)sx0;
        sxf1 = (float)sx1;
    }

    for (int q = 0; q < NGRP; q++) {      // 16 output-channel quads
        int acc[4][2] = {};
#pragma unroll
        for (int g = 0; g < NGRP; g++) {
            int4 w4 = *(const int4*)(s_w + g * COUT + q * 4);
            acc[0][0] = dp4a_us(xw[g][0], w4.x, acc[0][0]);
            acc[0][1] = dp4a_us(xw[g][1], w4.x, acc[0][1]);
            acc[1][0] = dp4a_us(xw[g][0], w4.y, acc[1][0]);
            acc[1][1] = dp4a_us(xw[g][1], w4.y, acc[1][1]);
            acc[2][0] = dp4a_us(xw[g][0], w4.z, acc[2][0]);
            acc[2][1] = dp4a_us(xw[g][1], w4.z, acc[2][1]);
            acc[3][0] = dp4a_us(xw[g][0], w4.w, acc[3][0]);
            acc[3][1] = dp4a_us(xw[g][1], w4.w, acc[3][1]);
        }
#pragma unroll
        for (int j = 0; j < 4; j++) {
            int o = q * 4 + j;
            float4 P = s_P[o];            // broadcast LDS.128: S, C0, C1
            float base0 = HASZP ? fmaf(P.z, sxf0, P.y) : P.y;
            float base1 = HASZP ? fmaf(P.z, sxf1, P.y) : P.y;
            float f0 = fmaf(P.x, (float)acc[j][0], base0);
            float f1 = fmaf(P.x, (float)acc[j][1], base1);
            float r0 = fminf(fmaxf(rintf(f0), 0.0f), 255.0f);
            float r1 = fminf(fmaxf(rintf(f1), 0.0f), 255.0f);
            o2[out_base + o * (HW / 2)] = make_float2(r0, r1);
        }
    }
}

__global__ __launch_bounds__(256, 3) void conv_fused(
    const int2*  __restrict__ x,
    float2*      __restrict__ out,
    const int4*  __restrict__ w,
    const float* __restrict__ wscale,
    const int*   __restrict__ wzp,
    const float* __restrict__ bias,
    const float* __restrict__ iscale,
    const float* __restrict__ oscale,
    const int*   __restrict__ izp_p,
    const int*   __restrict__ ozp_p)
{
    __shared__ int    s_w[NGRP * COUT];   // [group][o] packed s8 weights
    __shared__ float4 s_P[COUT];          // (S, C0, C1, 0) per output channel

    const int tid = threadIdx.x;
    int myzp = 0;

    // ---- inlined prep: threads 0..63 each build one output channel ----
    if (tid < COUT) {
        const int o = tid;
        int sum = 0;
#pragma unroll
        for (int g = 0; g < NGRP; g++) {
            int4 v = __ldg(w + o * NGRP + g);
            sum += v.x + v.y + v.z + v.w;
            s_w[g * COUT + o] = (int)pack4(v.x, v.y, v.z, v.w);
        }
        myzp = __ldg(wzp + o);
        float s   = iscale[0] * wscale[o] / oscale[0];
        float izp = (float)izp_p[0];
        float zw  = (float)myzp;
        // round(f)+ozp == round(f+ozp) for integer ozp -> fold ozp into C0
        float C0  = bias[o] / oscale[0]
                  + s * izp * (64.0f * zw - (float)sum)
                  + (float)ozp_p[0];
        s_P[o] = make_float4(s, C0, -s * zw, 0.0f);
    }
    // barrier (same as R5's __syncthreads) + block-wide OR of wzp != 0
    const int haszp = __syncthreads_or(myzp != 0);

    int gp = (blockIdx.x * 256 + tid) << 1;  // 2 consecutive w positions
    int b  = gp >> 14;                        // / HW
    int hw = gp & (HW - 1);

    const int2* xb = x + (b * (CIN * HW / 2) + (hw >> 1));
    const int out_base = b * COUT * (HW / 2) + (hw >> 1);   // float2 units

    if (haszp)
        conv_body<true>(xb, out, out_base, s_w, s_P);
    else
        conv_body<false>(xb, out, out_base, s_w, s_P);
}

extern "C" void kernel_launch(void* const* d_in, const int* in_sizes, int n_in,
                              void* d_out, int out_size) {
    // 0: x_quant (i32)  1: input_scale (f32)  2: input_zero_point (i32)
    // 3: weight_int8 (i32)  4: weight_scale (f32)  5: weight_zero_point (i32)
    // 6: bias_fp32 (f32)  7: output_scale (f32)  8: output_zero_point (i32)
    (void)in_sizes; (void)n_in; (void)out_size;

    // 524288 positions / 2 per thread / 256 threads = 1024 blocks (exact)
    conv_fused<<<1024, 256>>>((const int2*)d_in[0], (float2*)d_out,
                              (const int4*)d_in[3], (const float*)d_in[4],
                              (const int*)d_in[5], (const float*)d_in[6],
                              (const float*)d_in[1], (const float*)d_in[7],
                              (const int*)d_in[2], (const int*)d_in[8]);
}